// round 15
// baseline (speedup 1.0000x reference)
#include <cuda_runtime.h>
#include <cuda_bf16.h>
#include <cstdint>

// Problem constants (fixed shapes: B=2,S=2048,D=1024,H=4096,E=8,topk=2)
#define N_TOK 4096
#define D_DIM 1024
#define H_DIM 4096
#define E_NUM 8

#define TM 64
#define TN 64
#define TK 16
#define PAD 68   // smem row padding (floats), keeps float4 alignment, reduces bank conflicts

// -------- device scratch (static globals; no runtime allocation) --------
__device__ int   g_cnt[E_NUM];
__device__ int   g_j[E_NUM][N_TOK];    // j = token*2 + slot
__device__ float g_w[E_NUM][N_TOK];    // renormalized combine weight
__device__ float g_hbuf[(size_t)2 * N_TOK * H_DIM];  // 128 MB: per-(token,slot) hidden
__device__ float g_obuf[(size_t)2 * N_TOK * D_DIM];  //  32 MB: per-(token,slot) output

// ----------------------------------------------------------------------
__global__ void zero_cnt_kernel() {
    if (threadIdx.x < E_NUM) g_cnt[threadIdx.x] = 0;
}

// One warp per token: router logits, softmax, top-2, scatter to expert lists.
__global__ __launch_bounds__(256) void router_kernel(
    const float* __restrict__ x, const float* __restrict__ Wr,
    float* __restrict__ logits_out)
{
    int gw   = (blockIdx.x * blockDim.x + threadIdx.x) >> 5;   // token id
    int lane = threadIdx.x & 31;
    if (gw >= N_TOK) return;
    const float* xr = x + (size_t)gw * D_DIM;

    float acc[E_NUM];
#pragma unroll
    for (int e = 0; e < E_NUM; e++) acc[e] = 0.f;

    for (int i = lane; i < D_DIM; i += 32) {
        float xv = xr[i];
#pragma unroll
        for (int e = 0; e < E_NUM; e++) acc[e] = fmaf(xv, Wr[e * D_DIM + i], acc[e]);
    }
#pragma unroll
    for (int e = 0; e < E_NUM; e++) {
#pragma unroll
        for (int o = 16; o > 0; o >>= 1) acc[e] += __shfl_xor_sync(0xffffffffu, acc[e], o);
    }

    if (lane == 0) {
        // write logits
#pragma unroll
        for (int e = 0; e < E_NUM; e++) logits_out[(size_t)gw * E_NUM + e] = acc[e];
        // softmax
        float mx = acc[0];
#pragma unroll
        for (int e = 1; e < E_NUM; e++) mx = fmaxf(mx, acc[e]);
        float p[E_NUM], s = 0.f;
#pragma unroll
        for (int e = 0; e < E_NUM; e++) { p[e] = __expf(acc[e] - mx); s += p[e]; }
        float inv = 1.f / s;
#pragma unroll
        for (int e = 0; e < E_NUM; e++) p[e] *= inv;
        // top-2 (strict > keeps lowest index on ties, matching lax.top_k)
        int i0 = 0;
#pragma unroll
        for (int e = 1; e < E_NUM; e++) if (p[e] > p[i0]) i0 = e;
        int i1 = -1;
#pragma unroll
        for (int e = 0; e < E_NUM; e++) {
            if (e == i0) continue;
            if (i1 < 0 || p[e] > p[i1]) i1 = e;
        }
        float w0 = p[i0], w1 = p[i1];
        float rs = 1.f / (w0 + w1);
        w0 *= rs; w1 *= rs;

        int pos0 = atomicAdd(&g_cnt[i0], 1);
        g_j[i0][pos0] = gw * 2 + 0;  g_w[i0][pos0] = w0;
        int pos1 = atomicAdd(&g_cnt[i1], 1);
        g_j[i1][pos1] = gw * 2 + 1;  g_w[i1][pos1] = w1;
    }
}

// Pass 1: for expert e, gathered token tile [TM] x H tile [TN], K = D.
// Computes silu(x Wg^T) * (x Wu^T) * w  -> g_hbuf[j][h]
__global__ __launch_bounds__(256) void expert_up_kernel(
    const float* __restrict__ x, const float* __restrict__ Wg,
    const float* __restrict__ Wu)
{
    const int e  = blockIdx.x >> 6;        // 64 row-tiles per expert max
    const int rt = blockIdx.x & 63;
    const int cnt = g_cnt[e];
    const int rowbase = rt * TM;
    if (rowbase >= cnt) return;
    const int hbase = blockIdx.y * TN;

    __shared__ float As[TK][PAD];
    __shared__ float Bg[TK][PAD];
    __shared__ float Bu[TK][PAD];
    __shared__ int   s_j[TM];
    __shared__ float s_w[TM];

    const int tid = threadIdx.x;
    if (tid < TM) {
        int r = rowbase + tid;
        s_j[tid] = (r < cnt) ? g_j[e][r] : -1;
        s_w[tid] = (r < cnt) ? g_w[e][r] : 0.f;
    }
    __syncthreads();

    const float* wg = Wg + (size_t)e * H_DIM * D_DIM;
    const float* wu = Wu + (size_t)e * H_DIM * D_DIM;

    const int lm = tid >> 2;     // 0..63 : tile row for staging loads
    const int lc = tid & 3;      // 0..3  : 16B chunk within TK
    const int tx = tid & 15;     // micro-tile n
    const int ty = tid >> 4;     // micro-tile m

    const int aj = s_j[lm];
    const float* arow  = x  + (size_t)((aj >= 0 ? (aj >> 1) : 0)) * D_DIM;
    const float* bgrow = wg + (size_t)(hbase + lm) * D_DIM;
    const float* burow = wu + (size_t)(hbase + lm) * D_DIM;

    float accg[4][4], accu[4][4];
#pragma unroll
    for (int i = 0; i < 4; i++)
#pragma unroll
        for (int j2 = 0; j2 < 4; j2++) { accg[i][j2] = 0.f; accu[i][j2] = 0.f; }

    for (int k0 = 0; k0 < D_DIM; k0 += TK) {
        float4 av = (aj >= 0) ? *(const float4*)(arow + k0 + lc * 4)
                              : make_float4(0.f, 0.f, 0.f, 0.f);
        float4 gv = *(const float4*)(bgrow + k0 + lc * 4);
        float4 uv = *(const float4*)(burow + k0 + lc * 4);
        __syncthreads();
        As[lc * 4 + 0][lm] = av.x; As[lc * 4 + 1][lm] = av.y;
        As[lc * 4 + 2][lm] = av.z; As[lc * 4 + 3][lm] = av.w;
        Bg[lc * 4 + 0][lm] = gv.x; Bg[lc * 4 + 1][lm] = gv.y;
        Bg[lc * 4 + 2][lm] = gv.z; Bg[lc * 4 + 3][lm] = gv.w;
        Bu[lc * 4 + 0][lm] = uv.x; Bu[lc * 4 + 1][lm] = uv.y;
        Bu[lc * 4 + 2][lm] = uv.z; Bu[lc * 4 + 3][lm] = uv.w;
        __syncthreads();
#pragma unroll
        for (int k = 0; k < TK; k++) {
            float4 a  = *(const float4*)&As[k][ty * 4];
            float4 bg = *(const float4*)&Bg[k][tx * 4];
            float4 bu = *(const float4*)&Bu[k][tx * 4];
            float am[4] = {a.x, a.y, a.z, a.w};
            float bgn[4] = {bg.x, bg.y, bg.z, bg.w};
            float bun[4] = {bu.x, bu.y, bu.z, bu.w};
#pragma unroll
            for (int mi = 0; mi < 4; mi++) {
#pragma unroll
                for (int ni = 0; ni < 4; ni++) {
                    accg[mi][ni] = fmaf(am[mi], bgn[ni], accg[mi][ni]);
                    accu[mi][ni] = fmaf(am[mi], bun[ni], accu[mi][ni]);
                }
            }
        }
    }

    // epilogue: h = silu(g) * u * w
#pragma unroll
    for (int mi = 0; mi < 4; mi++) {
        int lr = ty * 4 + mi;
        if (rowbase + lr < cnt) {
            int jj = s_j[lr];
            float w = s_w[lr];
            float* o = g_hbuf + (size_t)jj * H_DIM + hbase + tx * 4;
            float4 hv;
            {
                float g = accg[mi][0]; hv.x = (g / (1.f + __expf(-g))) * accu[mi][0] * w;
                g = accg[mi][1];       hv.y = (g / (1.f + __expf(-g))) * accu[mi][1] * w;
                g = accg[mi][2];       hv.z = (g / (1.f + __expf(-g))) * accu[mi][2] * w;
                g = accg[mi][3];       hv.w = (g / (1.f + __expf(-g))) * accu[mi][3] * w;
            }
            *(float4*)o = hv;
        }
    }
}

// Pass 2: Obuf[j][d] = Hbuf[j][:] @ Wd[e]^T  (weight already folded into Hbuf)
__global__ __launch_bounds__(256) void expert_down_kernel(
    const float* __restrict__ Wd)
{
    const int e  = blockIdx.x >> 6;
    const int rt = blockIdx.x & 63;
    const int cnt = g_cnt[e];
    const int rowbase = rt * TM;
    if (rowbase >= cnt) return;
    const int dbase = blockIdx.y * TN;

    __shared__ float As[TK][PAD];
    __shared__ float Bd[TK][PAD];
    __shared__ int   s_j[TM];

    const int tid = threadIdx.x;
    if (tid < TM) {
        int r = rowbase + tid;
        s_j[tid] = (r < cnt) ? g_j[e][r] : -1;
    }
    __syncthreads();

    const float* wd = Wd + (size_t)e * D_DIM * H_DIM;

    const int lm = tid >> 2;
    const int lc = tid & 3;
    const int tx = tid & 15;
    const int ty = tid >> 4;

    const int aj = s_j[lm];
    const float* arow  = g_hbuf + (size_t)(aj >= 0 ? aj : 0) * H_DIM;
    const float* bdrow = wd + (size_t)(dbase + lm) * H_DIM;

    float acc[4][4];
#pragma unroll
    for (int i = 0; i < 4; i++)
#pragma unroll
        for (int j2 = 0; j2 < 4; j2++) acc[i][j2] = 0.f;

    for (int k0 = 0; k0 < H_DIM; k0 += TK) {
        float4 av = (aj >= 0) ? *(const float4*)(arow + k0 + lc * 4)
                              : make_float4(0.f, 0.f, 0.f, 0.f);
        float4 bv = *(const float4*)(bdrow + k0 + lc * 4);
        __syncthreads();
        As[lc * 4 + 0][lm] = av.x; As[lc * 4 + 1][lm] = av.y;
        As[lc * 4 + 2][lm] = av.z; As[lc * 4 + 3][lm] = av.w;
        Bd[lc * 4 + 0][lm] = bv.x; Bd[lc * 4 + 1][lm] = bv.y;
        Bd[lc * 4 + 2][lm] = bv.z; Bd[lc * 4 + 3][lm] = bv.w;
        __syncthreads();
#pragma unroll
        for (int k = 0; k < TK; k++) {
            float4 a = *(const float4*)&As[k][ty * 4];
            float4 b = *(const float4*)&Bd[k][tx * 4];
            float am[4] = {a.x, a.y, a.z, a.w};
            float bn[4] = {b.x, b.y, b.z, b.w};
#pragma unroll
            for (int mi = 0; mi < 4; mi++) {
#pragma unroll
                for (int ni = 0; ni < 4; ni++)
                    acc[mi][ni] = fmaf(am[mi], bn[ni], acc[mi][ni]);
            }
        }
    }

#pragma unroll
    for (int mi = 0; mi < 4; mi++) {
        int lr = ty * 4 + mi;
        if (rowbase + lr < cnt) {
            int jj = s_j[lr];
            float* o = g_obuf + (size_t)jj * D_DIM + dbase + tx * 4;
            float4 v = make_float4(acc[mi][0], acc[mi][1], acc[mi][2], acc[mi][3]);
            *(float4*)o = v;
        }
    }
}

// out[n][d] = Obuf[2n][d] + Obuf[2n+1][d]
__global__ __launch_bounds__(256) void combine_kernel(float* __restrict__ out) {
    size_t i = (size_t)blockIdx.x * blockDim.x + threadIdx.x;   // float4 index
    size_t total = (size_t)N_TOK * D_DIM / 4;
    if (i >= total) return;
    size_t f = i * 4;
    size_t n = f / D_DIM;
    size_t d = f % D_DIM;
    const float4 a = *(const float4*)&g_obuf[(size_t)(2 * n) * D_DIM + d];
    const float4 b = *(const float4*)&g_obuf[(size_t)(2 * n + 1) * D_DIM + d];
    float4 r = make_float4(a.x + b.x, a.y + b.y, a.z + b.z, a.w + b.w);
    *(float4*)&out[f] = r;
}

extern "C" void kernel_launch(void* const* d_in, const int* in_sizes, int n_in,
                              void* d_out, int out_size) {
    const float* x  = (const float*)d_in[0];  // [N, D]
    const float* Wr = (const float*)d_in[1];  // [E, D]
    const float* Wg = (const float*)d_in[2];  // [E, H, D]
    const float* Wu = (const float*)d_in[3];  // [E, H, D]
    const float* Wd = (const float*)d_in[4];  // [E, D, H]
    float* out = (float*)d_out;               // [N*D] then [N*E] router logits

    float* logits_out = out + (size_t)N_TOK * D_DIM;

    zero_cnt_kernel<<<1, 32>>>();
    router_kernel<<<N_TOK / 8, 256>>>(x, Wr, logits_out);
    expert_up_kernel<<<dim3(E_NUM * (N_TOK / TM), H_DIM / TN), 256>>>(x, Wg, Wu);
    expert_down_kernel<<<dim3(E_NUM * (N_TOK / TM), D_DIM / TN), 256>>>(Wd);
    combine_kernel<<<(N_TOK * D_DIM / 4 + 255) / 256, 256>>>(out);
}

// round 16
// speedup vs baseline: 1.0005x; 1.0005x over previous
#include <cuda_runtime.h>
#include <cuda_bf16.h>
#include <cstdint>

// Problem constants (fixed shapes: B=2,S=2048,D=1024,H=4096,E=8,topk=2)
#define N_TOK 4096
#define D_DIM 1024
#define H_DIM 4096
#define E_NUM 8

#define TM 64
#define TN 64
#define TK 16
#define PAD 68   // smem row padding (floats), keeps float4 alignment, reduces bank conflicts

// -------- device scratch (static globals; no runtime allocation) --------
__device__ int   g_cnt[E_NUM];
__device__ int   g_j[E_NUM][N_TOK];    // j = token*2 + slot
__device__ float g_w[E_NUM][N_TOK];    // renormalized combine weight
__device__ float g_hbuf[(size_t)2 * N_TOK * H_DIM];  // 128 MB: per-(token,slot) hidden
__device__ float g_obuf[(size_t)2 * N_TOK * D_DIM];  //  32 MB: per-(token,slot) output

// ----------------------------------------------------------------------
__global__ void zero_cnt_kernel() {
    if (threadIdx.x < E_NUM) g_cnt[threadIdx.x] = 0;
}

// One warp per token: router logits, softmax, top-2, scatter to expert lists.
__global__ __launch_bounds__(256) void router_kernel(
    const float* __restrict__ x, const float* __restrict__ Wr,
    float* __restrict__ logits_out)
{
    int gw   = (blockIdx.x * blockDim.x + threadIdx.x) >> 5;   // token id
    int lane = threadIdx.x & 31;
    if (gw >= N_TOK) return;
    const float* xr = x + (size_t)gw * D_DIM;

    float acc[E_NUM];
#pragma unroll
    for (int e = 0; e < E_NUM; e++) acc[e] = 0.f;

    for (int i = lane; i < D_DIM; i += 32) {
        float xv = xr[i];
#pragma unroll
        for (int e = 0; e < E_NUM; e++) acc[e] = fmaf(xv, Wr[e * D_DIM + i], acc[e]);
    }
#pragma unroll
    for (int e = 0; e < E_NUM; e++) {
#pragma unroll
        for (int o = 16; o > 0; o >>= 1) acc[e] += __shfl_xor_sync(0xffffffffu, acc[e], o);
    }

    if (lane == 0) {
        // write logits
#pragma unroll
        for (int e = 0; e < E_NUM; e++) logits_out[(size_t)gw * E_NUM + e] = acc[e];
        // softmax
        float mx = acc[0];
#pragma unroll
        for (int e = 1; e < E_NUM; e++) mx = fmaxf(mx, acc[e]);
        float p[E_NUM], s = 0.f;
#pragma unroll
        for (int e = 0; e < E_NUM; e++) { p[e] = __expf(acc[e] - mx); s += p[e]; }
        float inv = 1.f / s;
#pragma unroll
        for (int e = 0; e < E_NUM; e++) p[e] *= inv;
        // top-2 (strict > keeps lowest index on ties, matching lax.top_k)
        int i0 = 0;
#pragma unroll
        for (int e = 1; e < E_NUM; e++) if (p[e] > p[i0]) i0 = e;
        int i1 = -1;
#pragma unroll
        for (int e = 0; e < E_NUM; e++) {
            if (e == i0) continue;
            if (i1 < 0 || p[e] > p[i1]) i1 = e;
        }
        float w0 = p[i0], w1 = p[i1];
        float rs = 1.f / (w0 + w1);
        w0 *= rs; w1 *= rs;

        int pos0 = atomicAdd(&g_cnt[i0], 1);
        g_j[i0][pos0] = gw * 2 + 0;  g_w[i0][pos0] = w0;
        int pos1 = atomicAdd(&g_cnt[i1], 1);
        g_j[i1][pos1] = gw * 2 + 1;  g_w[i1][pos1] = w1;
    }
}

// Pass 1: for expert e, gathered token tile [TM] x H tile [TN], K = D.
// Computes silu(x Wg^T) * (x Wu^T) * w  -> g_hbuf[j][h]
__global__ __launch_bounds__(256) void expert_up_kernel(
    const float* __restrict__ x, const float* __restrict__ Wg,
    const float* __restrict__ Wu)
{
    const int e  = blockIdx.x >> 6;        // 64 row-tiles per expert max
    const int rt = blockIdx.x & 63;
    const int cnt = g_cnt[e];
    const int rowbase = rt * TM;
    if (rowbase >= cnt) return;
    const int hbase = blockIdx.y * TN;

    __shared__ float As[TK][PAD];
    __shared__ float Bg[TK][PAD];
    __shared__ float Bu[TK][PAD];
    __shared__ int   s_j[TM];
    __shared__ float s_w[TM];

    const int tid = threadIdx.x;
    if (tid < TM) {
        int r = rowbase + tid;
        s_j[tid] = (r < cnt) ? g_j[e][r] : -1;
        s_w[tid] = (r < cnt) ? g_w[e][r] : 0.f;
    }
    __syncthreads();

    const float* wg = Wg + (size_t)e * H_DIM * D_DIM;
    const float* wu = Wu + (size_t)e * H_DIM * D_DIM;

    const int lm = tid >> 2;     // 0..63 : tile row for staging loads
    const int lc = tid & 3;      // 0..3  : 16B chunk within TK
    const int tx = tid & 15;     // micro-tile n
    const int ty = tid >> 4;     // micro-tile m

    const int aj = s_j[lm];
    const float* arow  = x  + (size_t)((aj >= 0 ? (aj >> 1) : 0)) * D_DIM;
    const float* bgrow = wg + (size_t)(hbase + lm) * D_DIM;
    const float* burow = wu + (size_t)(hbase + lm) * D_DIM;

    float accg[4][4], accu[4][4];
#pragma unroll
    for (int i = 0; i < 4; i++)
#pragma unroll
        for (int j2 = 0; j2 < 4; j2++) { accg[i][j2] = 0.f; accu[i][j2] = 0.f; }

    for (int k0 = 0; k0 < D_DIM; k0 += TK) {
        float4 av = (aj >= 0) ? *(const float4*)(arow + k0 + lc * 4)
                              : make_float4(0.f, 0.f, 0.f, 0.f);
        float4 gv = *(const float4*)(bgrow + k0 + lc * 4);
        float4 uv = *(const float4*)(burow + k0 + lc * 4);
        __syncthreads();
        As[lc * 4 + 0][lm] = av.x; As[lc * 4 + 1][lm] = av.y;
        As[lc * 4 + 2][lm] = av.z; As[lc * 4 + 3][lm] = av.w;
        Bg[lc * 4 + 0][lm] = gv.x; Bg[lc * 4 + 1][lm] = gv.y;
        Bg[lc * 4 + 2][lm] = gv.z; Bg[lc * 4 + 3][lm] = gv.w;
        Bu[lc * 4 + 0][lm] = uv.x; Bu[lc * 4 + 1][lm] = uv.y;
        Bu[lc * 4 + 2][lm] = uv.z; Bu[lc * 4 + 3][lm] = uv.w;
        __syncthreads();
#pragma unroll
        for (int k = 0; k < TK; k++) {
            float4 a  = *(const float4*)&As[k][ty * 4];
            float4 bg = *(const float4*)&Bg[k][tx * 4];
            float4 bu = *(const float4*)&Bu[k][tx * 4];
            float am[4] = {a.x, a.y, a.z, a.w};
            float bgn[4] = {bg.x, bg.y, bg.z, bg.w};
            float bun[4] = {bu.x, bu.y, bu.z, bu.w};
#pragma unroll
            for (int mi = 0; mi < 4; mi++) {
#pragma unroll
                for (int ni = 0; ni < 4; ni++) {
                    accg[mi][ni] = fmaf(am[mi], bgn[ni], accg[mi][ni]);
                    accu[mi][ni] = fmaf(am[mi], bun[ni], accu[mi][ni]);
                }
            }
        }
    }

    // epilogue: h = silu(g) * u * w
#pragma unroll
    for (int mi = 0; mi < 4; mi++) {
        int lr = ty * 4 + mi;
        if (rowbase + lr < cnt) {
            int jj = s_j[lr];
            float w = s_w[lr];
            float* o = g_hbuf + (size_t)jj * H_DIM + hbase + tx * 4;
            float4 hv;
            {
                float g = accg[mi][0]; hv.x = (g / (1.f + __expf(-g))) * accu[mi][0] * w;
                g = accg[mi][1];       hv.y = (g / (1.f + __expf(-g))) * accu[mi][1] * w;
                g = accg[mi][2];       hv.z = (g / (1.f + __expf(-g))) * accu[mi][2] * w;
                g = accg[mi][3];       hv.w = (g / (1.f + __expf(-g))) * accu[mi][3] * w;
            }
            *(float4*)o = hv;
        }
    }
}

// Pass 2: Obuf[j][d] = Hbuf[j][:] @ Wd[e]^T  (weight already folded into Hbuf)
__global__ __launch_bounds__(256) void expert_down_kernel(
    const float* __restrict__ Wd)
{
    const int e  = blockIdx.x >> 6;
    const int rt = blockIdx.x & 63;
    const int cnt = g_cnt[e];
    const int rowbase = rt * TM;
    if (rowbase >= cnt) return;
    const int dbase = blockIdx.y * TN;

    __shared__ float As[TK][PAD];
    __shared__ float Bd[TK][PAD];
    __shared__ int   s_j[TM];

    const int tid = threadIdx.x;
    if (tid < TM) {
        int r = rowbase + tid;
        s_j[tid] = (r < cnt) ? g_j[e][r] : -1;
    }
    __syncthreads();

    const float* wd = Wd + (size_t)e * D_DIM * H_DIM;

    const int lm = tid >> 2;
    const int lc = tid & 3;
    const int tx = tid & 15;
    const int ty = tid >> 4;

    const int aj = s_j[lm];
    const float* arow  = g_hbuf + (size_t)(aj >= 0 ? aj : 0) * H_DIM;
    const float* bdrow = wd + (size_t)(dbase + lm) * H_DIM;

    float acc[4][4];
#pragma unroll
    for (int i = 0; i < 4; i++)
#pragma unroll
        for (int j2 = 0; j2 < 4; j2++) acc[i][j2] = 0.f;

    for (int k0 = 0; k0 < H_DIM; k0 += TK) {
        float4 av = (aj >= 0) ? *(const float4*)(arow + k0 + lc * 4)
                              : make_float4(0.f, 0.f, 0.f, 0.f);
        float4 bv = *(const float4*)(bdrow + k0 + lc * 4);
        __syncthreads();
        As[lc * 4 + 0][lm] = av.x; As[lc * 4 + 1][lm] = av.y;
        As[lc * 4 + 2][lm] = av.z; As[lc * 4 + 3][lm] = av.w;
        Bd[lc * 4 + 0][lm] = bv.x; Bd[lc * 4 + 1][lm] = bv.y;
        Bd[lc * 4 + 2][lm] = bv.z; Bd[lc * 4 + 3][lm] = bv.w;
        __syncthreads();
#pragma unroll
        for (int k = 0; k < TK; k++) {
            float4 a = *(const float4*)&As[k][ty * 4];
            float4 b = *(const float4*)&Bd[k][tx * 4];
            float am[4] = {a.x, a.y, a.z, a.w};
            float bn[4] = {b.x, b.y, b.z, b.w};
#pragma unroll
            for (int mi = 0; mi < 4; mi++) {
#pragma unroll
                for (int ni = 0; ni < 4; ni++)
                    acc[mi][ni] = fmaf(am[mi], bn[ni], acc[mi][ni]);
            }
        }
    }

#pragma unroll
    for (int mi = 0; mi < 4; mi++) {
        int lr = ty * 4 + mi;
        if (rowbase + lr < cnt) {
            int jj = s_j[lr];
            float* o = g_obuf + (size_t)jj * D_DIM + dbase + tx * 4;
            float4 v = make_float4(acc[mi][0], acc[mi][1], acc[mi][2], acc[mi][3]);
            *(float4*)o = v;
        }
    }
}

// out[n][d] = Obuf[2n][d] + Obuf[2n+1][d]
__global__ __launch_bounds__(256) void combine_kernel(float* __restrict__ out) {
    size_t i = (size_t)blockIdx.x * blockDim.x + threadIdx.x;   // float4 index
    size_t total = (size_t)N_TOK * D_DIM / 4;
    if (i >= total) return;
    size_t f = i * 4;
    size_t n = f / D_DIM;
    size_t d = f % D_DIM;
    const float4 a = *(const float4*)&g_obuf[(size_t)(2 * n) * D_DIM + d];
    const float4 b = *(const float4*)&g_obuf[(size_t)(2 * n + 1) * D_DIM + d];
    float4 r = make_float4(a.x + b.x, a.y + b.y, a.z + b.z, a.w + b.w);
    *(float4*)&out[f] = r;
}

extern "C" void kernel_launch(void* const* d_in, const int* in_sizes, int n_in,
                              void* d_out, int out_size) {
    const float* x  = (const float*)d_in[0];  // [N, D]
    const float* Wr = (const float*)d_in[1];  // [E, D]
    const float* Wg = (const float*)d_in[2];  // [E, H, D]
    const float* Wu = (const float*)d_in[3];  // [E, H, D]
    const float* Wd = (const float*)d_in[4];  // [E, D, H]
    float* out = (float*)d_out;               // [N*D] then [N*E] router logits

    float* logits_out = out + (size_t)N_TOK * D_DIM;

    zero_cnt_kernel<<<1, 32>>>();
    router_kernel<<<N_TOK / 8, 256>>>(x, Wr, logits_out);
    expert_up_kernel<<<dim3(E_NUM * (N_TOK / TM), H_DIM / TN), 256>>>(x, Wg, Wu);
    expert_down_kernel<<<dim3(E_NUM * (N_TOK / TM), D_DIM / TN), 256>>>(Wd);
    combine_kernel<<<(N_TOK * D_DIM / 4 + 255) / 256, 256>>>(out);
}